// round 11
// baseline (speedup 1.0000x reference)
#include <cuda_runtime.h>
#include <cuda_bf16.h>
#include <math.h>

#define N_NODES 50000
#define N_EDGES 800000
#define E_TOT   (N_EDGES + N_NODES)   // edges + self loops = 850000
#define F       128                   // in/out feature dim
#define HEADS   4
#define HDIM    32
#define NEG_SLOPE 0.2f

// GEMM smem layout (tf32 staging, padded for conflict-free fragment LDS)
#define XS_STRIDE 132                 // 64 x 132 uint  (33792 B)
#define WS_STRIDE 136                 // 128 x 136 uint (69632 B)
#define GEMM_SMEM (64 * XS_STRIDE * 4 + 128 * WS_STRIDE * 4)   // 103424 B
#define TILES_PER_BLOCK 4             // 256 rows per block, W staged once

// ----------------------------------------------------------------------------
// Scratch (device globals; no allocation allowed)
// ----------------------------------------------------------------------------
__device__ float g_x0[N_NODES * F];      // layer ping buffer
__device__ float g_x1[N_NODES * F];      // layer pong buffer
__device__ float g_h [N_NODES * F];      // h = x @ W (fp32)
__device__ float g_as[N_NODES * HEADS];  // alpha_src per node
__device__ float g_ad[N_NODES * HEADS];  // alpha_dst per node
__device__ int   g_deg[N_NODES];
__device__ int   g_off[N_NODES + 1];
__device__ int   g_cur[N_NODES];
__device__ int   g_csr[E_TOT];           // src node per CSR slot (grouped by dst)

// ----------------------------------------------------------------------------
// tf32 / mma helpers
// ----------------------------------------------------------------------------
__device__ __forceinline__ unsigned int f2tf32(float f) {
    unsigned int u;
    asm("cvt.rna.tf32.f32 %0, %1;" : "=r"(u) : "f"(f));
    return u;
}
__device__ __forceinline__ void mma_tf32(float* c,
    unsigned int a0, unsigned int a1, unsigned int a2, unsigned int a3,
    unsigned int b0, unsigned int b1) {
    asm("mma.sync.aligned.m16n8k8.row.col.f32.tf32.tf32.f32 "
        "{%0,%1,%2,%3}, {%4,%5,%6,%7}, {%8,%9}, {%0,%1,%2,%3};"
        : "+f"(c[0]), "+f"(c[1]), "+f"(c[2]), "+f"(c[3])
        : "r"(a0), "r"(a1), "r"(a2), "r"(a3), "r"(b0), "r"(b1));
}

// ----------------------------------------------------------------------------
// CSR construction (edge_index is int32)
// ----------------------------------------------------------------------------
__global__ void hist_kernel(const int* __restrict__ ei, int* __restrict__ deg) {
    int i = blockIdx.x * blockDim.x + threadIdx.x;
    if (i >= E_TOT) return;
    int dst = (i < N_EDGES) ? ei[N_EDGES + i] : (i - N_EDGES);
    if (dst >= 0 && dst < N_NODES) atomicAdd(&deg[dst], 1);
}

// single-block exclusive scan over 50000 degrees
__global__ void scan_kernel(const int* __restrict__ deg, int* __restrict__ off,
                            int* __restrict__ cur) {
    __shared__ int part[1024];
    const int CH = (N_NODES + 1023) / 1024;  // 49
    int t = threadIdx.x;
    int b = t * CH;
    int e = min(b + CH, N_NODES);
    int s = 0;
    for (int i = b; i < e; i++) s += deg[i];
    part[t] = s;
    __syncthreads();
    for (int o = 1; o < 1024; o <<= 1) {
        int v = (t >= o) ? part[t - o] : 0;
        __syncthreads();
        part[t] += v;
        __syncthreads();
    }
    int run = (t == 0) ? 0 : part[t - 1];
    for (int i = b; i < e; i++) {
        off[i] = run;
        cur[i] = run;
        run += deg[i];
    }
    if (t == 0) off[N_NODES] = part[1023];
}

__global__ void fill_kernel(const int* __restrict__ ei, int* __restrict__ cur,
                            int* __restrict__ csr) {
    int i = blockIdx.x * blockDim.x + threadIdx.x;
    if (i >= E_TOT) return;
    int src, dst;
    if (i < N_EDGES) { src = ei[i]; dst = ei[N_EDGES + i]; }
    else             { src = i - N_EDGES; dst = src; }
    if (dst < 0 || dst >= N_NODES) return;
    if (src < 0) src = 0; if (src >= N_NODES) src = N_NODES - 1;
    int pos = atomicAdd(&cur[dst], 1);
    csr[pos] = src;
}

// ----------------------------------------------------------------------------
// tf32 tensor-core GEMM + alpha fusion, 4 row-tiles per block (W staged once).
// Per 64x128 tile: warp w owns rows (w%4)*16, cols (w/4)*64.
// Epilogue: C frags -> smem -> fused fp32 h-store + alpha dot + 8-lane butterfly.
// ----------------------------------------------------------------------------
__global__ __launch_bounds__(256) void gemm_tf32_alpha_kernel(
    const float* __restrict__ x, const float* __restrict__ W,
    const float* __restrict__ a_s, const float* __restrict__ a_d,
    float* __restrict__ h, float* __restrict__ out_s, float* __restrict__ out_d) {
    extern __shared__ unsigned int smem_u[];
    unsigned int* Xs = smem_u;                       // 64 x XS_STRIDE (reused as hs)
    unsigned int* Wsm = smem_u + 64 * XS_STRIDE;     // 128 x WS_STRIDE
    int t = threadIdx.x;

    // stage W once (tf32)
    const float4* W4 = reinterpret_cast<const float4*>(W);
#pragma unroll
    for (int i = 0; i < 16; i++) {
        int idx = t + i * 256;          // 4096 float4 slots (128 rows x 32)
        int r = idx >> 5, c4 = idx & 31;
        float4 v = W4[r * 32 + c4];
        uint4 u = make_uint4(f2tf32(v.x), f2tf32(v.y), f2tf32(v.z), f2tf32(v.w));
        *reinterpret_cast<uint4*>(Wsm + r * WS_STRIDE + c4 * 4) = u;
    }

    int warp = t >> 5, lane = t & 31;
    int gid = lane >> 2, tid4 = lane & 3;
    int r0 = (warp & 3) * 16;
    int j0 = (warp >> 2) * 64;
    int t_row = t >> 5, t_col = t & 31;
    float4 asv = reinterpret_cast<const float4*>(a_s)[t_col];
    float4 adv = reinterpret_cast<const float4*>(a_d)[t_col];
    int head = t_col >> 3;
    const float4* x4 = reinterpret_cast<const float4*>(x);
    float4* h4 = reinterpret_cast<float4*>(h);

    for (int sub = 0; sub < TILES_PER_BLOCK; sub++) {
        int row0 = blockIdx.x * (64 * TILES_PER_BLOCK) + sub * 64;
        if (row0 >= N_NODES) break;

        __syncthreads();   // protect Xs/hs reuse from previous epilogue; W visible
        // stage X tile (tf32)
#pragma unroll
        for (int i = 0; i < 8; i++) {
            int idx = t + i * 256;          // 2048 float4 slots (64 rows x 32)
            int r = idx >> 5, c4 = idx & 31;
            float4 v = make_float4(0.f, 0.f, 0.f, 0.f);
            if (row0 + r < N_NODES) v = x4[(size_t)(row0 + r) * 32 + c4];
            uint4 u = make_uint4(f2tf32(v.x), f2tf32(v.y), f2tf32(v.z), f2tf32(v.w));
            *reinterpret_cast<uint4*>(Xs + r * XS_STRIDE + c4 * 4) = u;
        }
        __syncthreads();

        float c[8][4];
#pragma unroll
        for (int nt = 0; nt < 8; nt++)
#pragma unroll
            for (int j = 0; j < 4; j++) c[nt][j] = 0.f;

#pragma unroll 2
        for (int k0 = 0; k0 < F; k0 += 8) {
            unsigned int a0 = Xs[(r0 + gid) * XS_STRIDE + k0 + tid4];
            unsigned int a1 = Xs[(r0 + gid + 8) * XS_STRIDE + k0 + tid4];
            unsigned int a2 = Xs[(r0 + gid) * XS_STRIDE + k0 + 4 + tid4];
            unsigned int a3 = Xs[(r0 + gid + 8) * XS_STRIDE + k0 + 4 + tid4];
#pragma unroll
            for (int nt = 0; nt < 8; nt++) {
                int jb = j0 + nt * 8;
                unsigned int b0 = Wsm[(k0 + tid4) * WS_STRIDE + jb + gid];
                unsigned int b1 = Wsm[(k0 + tid4 + 4) * WS_STRIDE + jb + gid];
                mma_tf32(c[nt], a0, a1, a2, a3, b0, b1);
            }
        }
        __syncthreads();

        // C frags -> smem (reuse Xs region as float hs[64][XS_STRIDE])
        float* hs = reinterpret_cast<float*>(smem_u);
#pragma unroll
        for (int nt = 0; nt < 8; nt++) {
            int jb = j0 + nt * 8 + tid4 * 2;
            *reinterpret_cast<float2*>(hs + (r0 + gid) * XS_STRIDE + jb) =
                make_float2(c[nt][0], c[nt][1]);
            *reinterpret_cast<float2*>(hs + (r0 + gid + 8) * XS_STRIDE + jb) =
                make_float2(c[nt][2], c[nt][3]);
        }
        __syncthreads();

        // fused h store + alpha
#pragma unroll
        for (int r = 0; r < 8; r++) {
            int row = row0 + t_row * 8 + r;
            float4 hv = *reinterpret_cast<float4*>(hs + (t_row * 8 + r) * XS_STRIDE + t_col * 4);
            if (row < N_NODES)
                h4[(size_t)row * 32 + t_col] = hv;
            float ps = hv.x * asv.x + hv.y * asv.y + hv.z * asv.z + hv.w * asv.w;
            float pd = hv.x * adv.x + hv.y * adv.y + hv.z * adv.z + hv.w * adv.w;
#pragma unroll
            for (int o = 1; o < 8; o <<= 1) {
                ps += __shfl_xor_sync(0xffffffffu, ps, o);
                pd += __shfl_xor_sync(0xffffffffu, pd, o);
            }
            if ((t_col & 7) == 0 && row < N_NODES) {
                out_s[row * HEADS + head] = ps;
                out_d[row * HEADS + head] = pd;
            }
        }
    }
}

// ----------------------------------------------------------------------------
// Fused softmax + aggregation (R4 reference version): one warp per dst node.
// lane covers channels 4*lane..4*lane+3; head = lane>>3.
// q identical across the 8 lanes of a head -> den needs no reduction.
// ----------------------------------------------------------------------------
__global__ __launch_bounds__(256) void agg_fused_kernel(
    const float* __restrict__ h, const int* __restrict__ off,
    const int* __restrict__ csr, const float* __restrict__ as,
    const float* __restrict__ ad, const float* __restrict__ bias,
    float* __restrict__ out) {
    int warp = threadIdx.x >> 5;
    int lane = threadIdx.x & 31;
    int n = blockIdx.x * 8 + warp;
    if (n >= N_NODES) return;

    int head = lane >> 3;
    float ad_h = ad[n * HEADS + head];
    const float4* h4 = reinterpret_cast<const float4*>(h);

    float4 acc = make_float4(0.f, 0.f, 0.f, 0.f);
    float den = 0.f;
    int s0 = off[n], s1 = off[n + 1];

    int pos = s0;
    for (; pos + 4 <= s1; pos += 4) {
        int sa = csr[pos];
        int sb = csr[pos + 1];
        int sc = csr[pos + 2];
        int sd = csr[pos + 3];
        float ea = as[sa * HEADS + head] + ad_h;
        float eb = as[sb * HEADS + head] + ad_h;
        float ec = as[sc * HEADS + head] + ad_h;
        float ed = as[sd * HEADS + head] + ad_h;
        ea = ea > 0.f ? ea : NEG_SLOPE * ea;
        eb = eb > 0.f ? eb : NEG_SLOPE * eb;
        ec = ec > 0.f ? ec : NEG_SLOPE * ec;
        ed = ed > 0.f ? ed : NEG_SLOPE * ed;
        float qa = __expf(ea), qb = __expf(eb), qc = __expf(ec), qd = __expf(ed);
        float4 ha = h4[(size_t)sa * 32 + lane];
        float4 hb = h4[(size_t)sb * 32 + lane];
        float4 hc = h4[(size_t)sc * 32 + lane];
        float4 hd = h4[(size_t)sd * 32 + lane];
        acc.x += qa * ha.x + qb * hb.x + qc * hc.x + qd * hd.x;
        acc.y += qa * ha.y + qb * hb.y + qc * hc.y + qd * hd.y;
        acc.z += qa * ha.z + qb * hb.z + qc * hc.z + qd * hd.z;
        acc.w += qa * ha.w + qb * hb.w + qc * hc.w + qd * hd.w;
        den += (qa + qb) + (qc + qd);
    }
    for (; pos < s1; pos++) {
        int sa = csr[pos];
        float e = as[sa * HEADS + head] + ad_h;
        e = e > 0.f ? e : NEG_SLOPE * e;
        float q = __expf(e);
        float4 ha = h4[(size_t)sa * 32 + lane];
        acc.x += q * ha.x; acc.y += q * ha.y;
        acc.z += q * ha.z; acc.w += q * ha.w;
        den += q;
    }

    float inv = 1.f / den;   // deg >= 1 (self loop), den > 0
    float4 bv = reinterpret_cast<const float4*>(bias)[lane];
    float4 o;
    o.x = fmaxf(acc.x * inv + bv.x, 0.f);
    o.y = fmaxf(acc.y * inv + bv.y, 0.f);
    o.z = fmaxf(acc.z * inv + bv.z, 0.f);
    o.w = fmaxf(acc.w * inv + bv.w, 0.f);
    reinterpret_cast<float4*>(out)[(size_t)n * 32 + lane] = o;
}

// ----------------------------------------------------------------------------
// Launch
// ----------------------------------------------------------------------------
extern "C" void kernel_launch(void* const* d_in, const int* in_sizes, int n_in,
                              void* d_out, int out_size) {
    const float* x    = (const float*)d_in[0];
    const int*   ei   = (const int*)d_in[1];
    const float* Ws   = (const float*)d_in[2];
    const float* a_s  = (const float*)d_in[3];
    const float* a_d  = (const float*)d_in[4];
    const float* bias = (const float*)d_in[5];
    float*       out  = (float*)d_out;

    void* pv;
    cudaGetSymbolAddress(&pv, g_x0);  float* x0  = (float*)pv;
    cudaGetSymbolAddress(&pv, g_x1);  float* x1  = (float*)pv;
    cudaGetSymbolAddress(&pv, g_h);   float* h   = (float*)pv;
    cudaGetSymbolAddress(&pv, g_as);  float* as  = (float*)pv;
    cudaGetSymbolAddress(&pv, g_ad);  float* ad  = (float*)pv;
    cudaGetSymbolAddress(&pv, g_deg); int*   deg = (int*)pv;
    cudaGetSymbolAddress(&pv, g_off); int*   off = (int*)pv;
    cudaGetSymbolAddress(&pv, g_cur); int*   cur = (int*)pv;
    cudaGetSymbolAddress(&pv, g_csr); int*   csr = (int*)pv;

    cudaFuncSetAttribute(gemm_tf32_alpha_kernel,
                         cudaFuncAttributeMaxDynamicSharedMemorySize, GEMM_SMEM);

    // CSR build (once; reused by all 3 layers)
    cudaMemsetAsync(deg, 0, N_NODES * sizeof(int));
    hist_kernel<<<(E_TOT + 255) / 256, 256>>>(ei, deg);
    scan_kernel<<<1, 1024>>>(deg, off, cur);
    fill_kernel<<<(E_TOT + 255) / 256, 256>>>(ei, cur, csr);

    const int gemm_grid = (N_NODES + 64 * TILES_PER_BLOCK - 1) / (64 * TILES_PER_BLOCK);
    for (int l = 0; l < 3; l++) {
        const float* xin = (l == 0) ? x : ((l == 1) ? x0 : x1);
        float* xout = (l == 0) ? x0 : ((l == 1) ? x1 : out);
        gemm_tf32_alpha_kernel<<<gemm_grid, 256, GEMM_SMEM>>>(
            xin, Ws + (size_t)l * F * F, a_s + l * F, a_d + l * F, h, as, ad);
        agg_fused_kernel<<<(N_NODES + 7) / 8, 256>>>(
            h, off, csr, as, ad, bias + l * F, xout);
    }
}

// round 12
// speedup vs baseline: 1.0508x; 1.0508x over previous
#include <cuda_runtime.h>
#include <cuda_bf16.h>
#include <math.h>

#define N_NODES 50000
#define N_EDGES 800000
#define E_TOT   (N_EDGES + N_NODES)   // edges + self loops = 850000
#define F       128                   // in/out feature dim
#define HEADS   4
#define HDIM    32
#define NEG_SLOPE 0.2f

// GEMM smem layout (tf32 staging, padded for conflict-free fragment LDS)
#define XS_STRIDE 132                 // 64 x 132 uint  (33792 B)
#define WS_STRIDE 136                 // 128 x 136 uint (69632 B)
#define GEMM_SMEM (64 * XS_STRIDE * 4 + 128 * WS_STRIDE * 4)   // 103424 B

// ----------------------------------------------------------------------------
// Scratch (device globals; no allocation allowed)
// ----------------------------------------------------------------------------
__device__ float        g_x0[N_NODES * F];      // layer ping buffer
__device__ float        g_x1[N_NODES * F];      // layer pong buffer
__device__ float        g_h [N_NODES * F];      // h = x @ W (fp32)
__device__ float        g_as[N_NODES * HEADS];  // alpha_src per node
__device__ float        g_ad[N_NODES * HEADS];  // alpha_dst per node
__device__ unsigned int g_wt[3 * F * F];        // pre-converted tf32 weights
__device__ int          g_deg[N_NODES];
__device__ int          g_off[N_NODES + 1];
__device__ int          g_cur[N_NODES];
__device__ int          g_csr[E_TOT];           // src node per CSR slot

// ----------------------------------------------------------------------------
// tf32 / mma helpers
// ----------------------------------------------------------------------------
__device__ __forceinline__ unsigned int f2tf32(float f) {
    unsigned int u;
    asm("cvt.rna.tf32.f32 %0, %1;" : "=r"(u) : "f"(f));
    return u;
}
__device__ __forceinline__ void mma_tf32(float* c,
    unsigned int a0, unsigned int a1, unsigned int a2, unsigned int a3,
    unsigned int b0, unsigned int b1) {
    asm("mma.sync.aligned.m16n8k8.row.col.f32.tf32.tf32.f32 "
        "{%0,%1,%2,%3}, {%4,%5,%6,%7}, {%8,%9}, {%0,%1,%2,%3};"
        : "+f"(c[0]), "+f"(c[1]), "+f"(c[2]), "+f"(c[3])
        : "r"(a0), "r"(a1), "r"(a2), "r"(a3), "r"(b0), "r"(b1));
}

// ----------------------------------------------------------------------------
// W pre-convert: all 3 layers' weights -> tf32 bits (once per launch)
// ----------------------------------------------------------------------------
__global__ void wconv_kernel(const float* __restrict__ Ws,
                             unsigned int* __restrict__ wt) {
    int i = blockIdx.x * blockDim.x + threadIdx.x;
    if (i < 3 * F * F) wt[i] = f2tf32(Ws[i]);
}

// ----------------------------------------------------------------------------
// CSR construction (edge_index is int32)
// ----------------------------------------------------------------------------
__global__ void hist_kernel(const int* __restrict__ ei, int* __restrict__ deg) {
    int i = blockIdx.x * blockDim.x + threadIdx.x;
    if (i >= E_TOT) return;
    int dst = (i < N_EDGES) ? ei[N_EDGES + i] : (i - N_EDGES);
    if (dst >= 0 && dst < N_NODES) atomicAdd(&deg[dst], 1);
}

// single-block exclusive scan over 50000 degrees
__global__ void scan_kernel(const int* __restrict__ deg, int* __restrict__ off,
                            int* __restrict__ cur) {
    __shared__ int part[1024];
    const int CH = (N_NODES + 1023) / 1024;  // 49
    int t = threadIdx.x;
    int b = t * CH;
    int e = min(b + CH, N_NODES);
    int s = 0;
    for (int i = b; i < e; i++) s += deg[i];
    part[t] = s;
    __syncthreads();
    for (int o = 1; o < 1024; o <<= 1) {
        int v = (t >= o) ? part[t - o] : 0;
        __syncthreads();
        part[t] += v;
        __syncthreads();
    }
    int run = (t == 0) ? 0 : part[t - 1];
    for (int i = b; i < e; i++) {
        off[i] = run;
        cur[i] = run;
        run += deg[i];
    }
    if (t == 0) off[N_NODES] = part[1023];
}

__global__ void fill_kernel(const int* __restrict__ ei, int* __restrict__ cur,
                            int* __restrict__ csr) {
    int i = blockIdx.x * blockDim.x + threadIdx.x;
    if (i >= E_TOT) return;
    int src, dst;
    if (i < N_EDGES) { src = ei[i]; dst = ei[N_EDGES + i]; }
    else             { src = i - N_EDGES; dst = src; }
    if (dst < 0 || dst >= N_NODES) return;
    if (src < 0) src = 0; if (src >= N_NODES) src = N_NODES - 1;
    int pos = atomicAdd(&cur[dst], 1);
    csr[pos] = src;
}

// ----------------------------------------------------------------------------
// tf32 tensor-core GEMM + alpha fusion (R10 structure: 64x128 tile per block).
// W staged from pre-converted tf32 bits (pure copy). Warp w: rows (w%4)*16,
// cols (w/4)*64. Epilogue: C -> smem -> fused h-store + alpha + butterfly.
// ----------------------------------------------------------------------------
__global__ __launch_bounds__(256) void gemm_tf32_alpha_kernel(
    const float* __restrict__ x, const unsigned int* __restrict__ wt,
    const float* __restrict__ a_s, const float* __restrict__ a_d,
    float* __restrict__ h, float* __restrict__ out_s, float* __restrict__ out_d) {
    extern __shared__ unsigned int smem_u[];
    unsigned int* Xs = smem_u;                       // 64 x XS_STRIDE (reused as hs)
    unsigned int* Wsm = smem_u + 64 * XS_STRIDE;     // 128 x WS_STRIDE
    int t = threadIdx.x;
    int row0 = blockIdx.x * 64;

    // stage X tile (tf32 convert on the fly)
    const float4* x4 = reinterpret_cast<const float4*>(x);
#pragma unroll
    for (int i = 0; i < 8; i++) {
        int idx = t + i * 256;          // 2048 float4 slots (64 rows x 32)
        int r = idx >> 5, c4 = idx & 31;
        float4 v = make_float4(0.f, 0.f, 0.f, 0.f);
        if (row0 + r < N_NODES) v = x4[(size_t)(row0 + r) * 32 + c4];
        uint4 u = make_uint4(f2tf32(v.x), f2tf32(v.y), f2tf32(v.z), f2tf32(v.w));
        *reinterpret_cast<uint4*>(Xs + r * XS_STRIDE + c4 * 4) = u;
    }
    // stage W (pure uint4 copy of pre-converted bits)
    const uint4* wt4 = reinterpret_cast<const uint4*>(wt);
#pragma unroll
    for (int i = 0; i < 16; i++) {
        int idx = t + i * 256;          // 4096 uint4 slots (128 rows x 32)
        int r = idx >> 5, c4 = idx & 31;
        *reinterpret_cast<uint4*>(Wsm + r * WS_STRIDE + c4 * 4) = wt4[r * 32 + c4];
    }
    __syncthreads();

    int warp = t >> 5, lane = t & 31;
    int gid = lane >> 2, tid4 = lane & 3;
    int r0 = (warp & 3) * 16;
    int j0 = (warp >> 2) * 64;

    float c[8][4];
#pragma unroll
    for (int nt = 0; nt < 8; nt++)
#pragma unroll
        for (int j = 0; j < 4; j++) c[nt][j] = 0.f;

#pragma unroll 2
    for (int k0 = 0; k0 < F; k0 += 8) {
        unsigned int a0 = Xs[(r0 + gid) * XS_STRIDE + k0 + tid4];
        unsigned int a1 = Xs[(r0 + gid + 8) * XS_STRIDE + k0 + tid4];
        unsigned int a2 = Xs[(r0 + gid) * XS_STRIDE + k0 + 4 + tid4];
        unsigned int a3 = Xs[(r0 + gid + 8) * XS_STRIDE + k0 + 4 + tid4];
#pragma unroll
        for (int nt = 0; nt < 8; nt++) {
            int jb = j0 + nt * 8;
            unsigned int b0 = Wsm[(k0 + tid4) * WS_STRIDE + jb + gid];
            unsigned int b1 = Wsm[(k0 + tid4 + 4) * WS_STRIDE + jb + gid];
            mma_tf32(c[nt], a0, a1, a2, a3, b0, b1);
        }
    }
    __syncthreads();

    // C frags -> smem (reuse Xs region as float hs[64][XS_STRIDE])
    float* hs = reinterpret_cast<float*>(smem_u);
#pragma unroll
    for (int nt = 0; nt < 8; nt++) {
        int jb = j0 + nt * 8 + tid4 * 2;
        *reinterpret_cast<float2*>(hs + (r0 + gid) * XS_STRIDE + jb) =
            make_float2(c[nt][0], c[nt][1]);
        *reinterpret_cast<float2*>(hs + (r0 + gid + 8) * XS_STRIDE + jb) =
            make_float2(c[nt][2], c[nt][3]);
    }
    __syncthreads();

    // fused h store + alpha: thread (t_row, t_col) handles rows t_row*8..+8,
    // channels t_col*4..+4; head = t_col>>3, butterfly over 8 lanes.
    int t_row = t >> 5, t_col = t & 31;
    float4 asv = reinterpret_cast<const float4*>(a_s)[t_col];
    float4 adv = reinterpret_cast<const float4*>(a_d)[t_col];
    int head = t_col >> 3;
    float4* h4 = reinterpret_cast<float4*>(h);
#pragma unroll
    for (int r = 0; r < 8; r++) {
        int row = row0 + t_row * 8 + r;
        float4 hv = *reinterpret_cast<float4*>(hs + (t_row * 8 + r) * XS_STRIDE + t_col * 4);
        if (row < N_NODES)
            h4[(size_t)row * 32 + t_col] = hv;
        float ps = hv.x * asv.x + hv.y * asv.y + hv.z * asv.z + hv.w * asv.w;
        float pd = hv.x * adv.x + hv.y * adv.y + hv.z * adv.z + hv.w * adv.w;
#pragma unroll
        for (int o = 1; o < 8; o <<= 1) {
            ps += __shfl_xor_sync(0xffffffffu, ps, o);
            pd += __shfl_xor_sync(0xffffffffu, pd, o);
        }
        if ((t_col & 7) == 0 && row < N_NODES) {
            out_s[row * HEADS + head] = ps;
            out_d[row * HEADS + head] = pd;
        }
    }
}

// ----------------------------------------------------------------------------
// Fused softmax + aggregation (R4 reference version): one warp per dst node.
// lane covers channels 4*lane..4*lane+3; head = lane>>3.
// q identical across the 8 lanes of a head -> den needs no reduction.
// ----------------------------------------------------------------------------
__global__ __launch_bounds__(256) void agg_fused_kernel(
    const float* __restrict__ h, const int* __restrict__ off,
    const int* __restrict__ csr, const float* __restrict__ as,
    const float* __restrict__ ad, const float* __restrict__ bias,
    float* __restrict__ out) {
    int warp = threadIdx.x >> 5;
    int lane = threadIdx.x & 31;
    int n = blockIdx.x * 8 + warp;
    if (n >= N_NODES) return;

    int head = lane >> 3;
    float ad_h = ad[n * HEADS + head];
    const float4* h4 = reinterpret_cast<const float4*>(h);

    float4 acc = make_float4(0.f, 0.f, 0.f, 0.f);
    float den = 0.f;
    int s0 = off[n], s1 = off[n + 1];

    int pos = s0;
    for (; pos + 4 <= s1; pos += 4) {
        int sa = csr[pos];
        int sb = csr[pos + 1];
        int sc = csr[pos + 2];
        int sd = csr[pos + 3];
        float ea = as[sa * HEADS + head] + ad_h;
        float eb = as[sb * HEADS + head] + ad_h;
        float ec = as[sc * HEADS + head] + ad_h;
        float ed = as[sd * HEADS + head] + ad_h;
        ea = ea > 0.f ? ea : NEG_SLOPE * ea;
        eb = eb > 0.f ? eb : NEG_SLOPE * eb;
        ec = ec > 0.f ? ec : NEG_SLOPE * ec;
        ed = ed > 0.f ? ed : NEG_SLOPE * ed;
        float qa = __expf(ea), qb = __expf(eb), qc = __expf(ec), qd = __expf(ed);
        float4 ha = h4[(size_t)sa * 32 + lane];
        float4 hb = h4[(size_t)sb * 32 + lane];
        float4 hc = h4[(size_t)sc * 32 + lane];
        float4 hd = h4[(size_t)sd * 32 + lane];
        acc.x += qa * ha.x + qb * hb.x + qc * hc.x + qd * hd.x;
        acc.y += qa * ha.y + qb * hb.y + qc * hc.y + qd * hd.y;
        acc.z += qa * ha.z + qb * hb.z + qc * hc.z + qd * hd.z;
        acc.w += qa * ha.w + qb * hb.w + qc * hc.w + qd * hd.w;
        den += (qa + qb) + (qc + qd);
    }
    for (; pos < s1; pos++) {
        int sa = csr[pos];
        float e = as[sa * HEADS + head] + ad_h;
        e = e > 0.f ? e : NEG_SLOPE * e;
        float q = __expf(e);
        float4 ha = h4[(size_t)sa * 32 + lane];
        acc.x += q * ha.x; acc.y += q * ha.y;
        acc.z += q * ha.z; acc.w += q * ha.w;
        den += q;
    }

    float inv = 1.f / den;   // deg >= 1 (self loop), den > 0
    float4 bv = reinterpret_cast<const float4*>(bias)[lane];
    float4 o;
    o.x = fmaxf(acc.x * inv + bv.x, 0.f);
    o.y = fmaxf(acc.y * inv + bv.y, 0.f);
    o.z = fmaxf(acc.z * inv + bv.z, 0.f);
    o.w = fmaxf(acc.w * inv + bv.w, 0.f);
    reinterpret_cast<float4*>(out)[(size_t)n * 32 + lane] = o;
}

// ----------------------------------------------------------------------------
// Launch
// ----------------------------------------------------------------------------
extern "C" void kernel_launch(void* const* d_in, const int* in_sizes, int n_in,
                              void* d_out, int out_size) {
    const float* x    = (const float*)d_in[0];
    const int*   ei   = (const int*)d_in[1];
    const float* Ws   = (const float*)d_in[2];
    const float* a_s  = (const float*)d_in[3];
    const float* a_d  = (const float*)d_in[4];
    const float* bias = (const float*)d_in[5];
    float*       out  = (float*)d_out;

    void* pv;
    cudaGetSymbolAddress(&pv, g_x0);  float* x0  = (float*)pv;
    cudaGetSymbolAddress(&pv, g_x1);  float* x1  = (float*)pv;
    cudaGetSymbolAddress(&pv, g_h);   float* h   = (float*)pv;
    cudaGetSymbolAddress(&pv, g_as);  float* as  = (float*)pv;
    cudaGetSymbolAddress(&pv, g_ad);  float* ad  = (float*)pv;
    cudaGetSymbolAddress(&pv, g_wt);  unsigned int* wt = (unsigned int*)pv;
    cudaGetSymbolAddress(&pv, g_deg); int*   deg = (int*)pv;
    cudaGetSymbolAddress(&pv, g_off); int*   off = (int*)pv;
    cudaGetSymbolAddress(&pv, g_cur); int*   cur = (int*)pv;
    cudaGetSymbolAddress(&pv, g_csr); int*   csr = (int*)pv;

    cudaFuncSetAttribute(gemm_tf32_alpha_kernel,
                         cudaFuncAttributeMaxDynamicSharedMemorySize, GEMM_SMEM);
    cudaFuncSetAttribute(gemm_tf32_alpha_kernel,
                         cudaFuncAttributePreferredSharedMemoryCarveout, 100);

    // W pre-convert (all layers) + CSR build (once; reused by all 3 layers)
    wconv_kernel<<<(3 * F * F + 255) / 256, 256>>>(Ws, wt);
    cudaMemsetAsync(deg, 0, N_NODES * sizeof(int));
    hist_kernel<<<(E_TOT + 255) / 256, 256>>>(ei, deg);
    scan_kernel<<<1, 1024>>>(deg, off, cur);
    fill_kernel<<<(E_TOT + 255) / 256, 256>>>(ei, cur, csr);

    for (int l = 0; l < 3; l++) {
        const float* xin = (l == 0) ? x : ((l == 1) ? x0 : x1);
        float* xout = (l == 0) ? x0 : ((l == 1) ? x1 : out);
        gemm_tf32_alpha_kernel<<<(N_NODES + 63) / 64, 256, GEMM_SMEM>>>(
            xin, wt + (size_t)l * F * F, a_s + l * F, a_d + l * F, h, as, ad);
        agg_fused_kernel<<<(N_NODES + 7) / 8, 256>>>(
            h, off, csr, as, ad, bias + l * F, xout);
    }
}

// round 13
// speedup vs baseline: 1.0584x; 1.0072x over previous
#include <cuda_runtime.h>
#include <cuda_bf16.h>
#include <math.h>

#define N_NODES 50000
#define N_EDGES 800000
#define E_TOT   (N_EDGES + N_NODES)   // edges + self loops = 850000
#define F       128                   // in/out feature dim
#define HEADS   4
#define HDIM    32
#define NEG_SLOPE 0.2f

// GEMM smem layout (tf32 staging, padded for conflict-free fragment LDS)
#define XS_STRIDE 132                 // 64 x 132 uint  (33792 B)
#define WS_STRIDE 136                 // 128 x 136 uint (69632 B)
#define GEMM_SMEM (64 * XS_STRIDE * 4 + 128 * WS_STRIDE * 4)   // 103424 B

// ----------------------------------------------------------------------------
// Scratch (device globals; no allocation allowed)
// ----------------------------------------------------------------------------
__device__ float        g_x0[N_NODES * F];      // layer ping buffer
__device__ float        g_x1[N_NODES * F];      // layer pong buffer
__device__ float        g_h [N_NODES * F];      // h = x @ W (fp32)
__device__ float        g_as[N_NODES * HEADS];  // alpha_src per node
__device__ float        g_ad[N_NODES * HEADS];  // alpha_dst per node
__device__ unsigned int g_wt[3 * F * F];        // pre-converted tf32 weights
__device__ int          g_deg[N_NODES];
__device__ int          g_off[N_NODES + 1];
__device__ int          g_cur[N_NODES];
__device__ int          g_csr[E_TOT];           // src node per CSR slot

// ----------------------------------------------------------------------------
// tf32 / mma helpers
// ----------------------------------------------------------------------------
__device__ __forceinline__ unsigned int f2tf32(float f) {
    unsigned int u;
    asm("cvt.rna.tf32.f32 %0, %1;" : "=r"(u) : "f"(f));
    return u;
}
__device__ __forceinline__ void mma_tf32(float* c,
    unsigned int a0, unsigned int a1, unsigned int a2, unsigned int a3,
    unsigned int b0, unsigned int b1) {
    asm("mma.sync.aligned.m16n8k8.row.col.f32.tf32.tf32.f32 "
        "{%0,%1,%2,%3}, {%4,%5,%6,%7}, {%8,%9}, {%0,%1,%2,%3};"
        : "+f"(c[0]), "+f"(c[1]), "+f"(c[2]), "+f"(c[3])
        : "r"(a0), "r"(a1), "r"(a2), "r"(a3), "r"(b0), "r"(b1));
}

// ----------------------------------------------------------------------------
// W pre-convert: all 3 layers' weights -> tf32 bits (once per launch)
// ----------------------------------------------------------------------------
__global__ void wconv_kernel(const float* __restrict__ Ws,
                             unsigned int* __restrict__ wt) {
    int i = blockIdx.x * blockDim.x + threadIdx.x;
    if (i < 3 * F * F) wt[i] = f2tf32(Ws[i]);
}

// ----------------------------------------------------------------------------
// CSR construction (edge_index is int32).
// deg starts at 1 (self loop folded in); hist covers real edges only, int4.
// ----------------------------------------------------------------------------
__global__ void deg_one_kernel(int* __restrict__ deg) {
    int i = blockIdx.x * blockDim.x + threadIdx.x;
    if (i < N_NODES) deg[i] = 1;
}

__global__ void hist_kernel(const int* __restrict__ ei, int* __restrict__ deg) {
    int i = blockIdx.x * blockDim.x + threadIdx.x;
    if (i >= N_EDGES / 4) return;
    int4 d4 = reinterpret_cast<const int4*>(ei + N_EDGES)[i];
    if (d4.x >= 0 && d4.x < N_NODES) atomicAdd(&deg[d4.x], 1);
    if (d4.y >= 0 && d4.y < N_NODES) atomicAdd(&deg[d4.y], 1);
    if (d4.z >= 0 && d4.z < N_NODES) atomicAdd(&deg[d4.z], 1);
    if (d4.w >= 0 && d4.w < N_NODES) atomicAdd(&deg[d4.w], 1);
}

// single-block exclusive scan over 50000 degrees
__global__ void scan_kernel(const int* __restrict__ deg, int* __restrict__ off,
                            int* __restrict__ cur) {
    __shared__ int part[1024];
    const int CH = (N_NODES + 1023) / 1024;  // 49
    int t = threadIdx.x;
    int b = t * CH;
    int e = min(b + CH, N_NODES);
    int s = 0;
    for (int i = b; i < e; i++) s += deg[i];
    part[t] = s;
    __syncthreads();
    for (int o = 1; o < 1024; o <<= 1) {
        int v = (t >= o) ? part[t - o] : 0;
        __syncthreads();
        part[t] += v;
        __syncthreads();
    }
    int run = (t == 0) ? 0 : part[t - 1];
    for (int i = b; i < e; i++) {
        off[i] = run;
        cur[i] = run;
        run += deg[i];
    }
    if (t == 0) off[N_NODES] = part[1023];
}

__device__ __forceinline__ void fill_one(int src, int dst,
                                         int* __restrict__ cur,
                                         int* __restrict__ csr) {
    if (dst < 0 || dst >= N_NODES) return;
    if (src < 0) src = 0; if (src >= N_NODES) src = N_NODES - 1;
    int pos = atomicAdd(&cur[dst], 1);
    csr[pos] = src;
}

__global__ void fill_kernel(const int* __restrict__ ei, int* __restrict__ cur,
                            int* __restrict__ csr) {
    int i = blockIdx.x * blockDim.x + threadIdx.x;
    if (i < N_EDGES / 4) {
        int4 s4 = reinterpret_cast<const int4*>(ei)[i];
        int4 d4 = reinterpret_cast<const int4*>(ei + N_EDGES)[i];
        fill_one(s4.x, d4.x, cur, csr);
        fill_one(s4.y, d4.y, cur, csr);
        fill_one(s4.z, d4.z, cur, csr);
        fill_one(s4.w, d4.w, cur, csr);
    } else if (i < E_TOT / 4) {
        int node = i * 4 - N_EDGES;
#pragma unroll
        for (int j = 0; j < 4; j++) {
            int pos = atomicAdd(&cur[node + j], 1);
            csr[pos] = node + j;
        }
    }
}

// ----------------------------------------------------------------------------
// tf32 tensor-core GEMM + alpha fusion (64x128 tile per block).
// W staged from pre-converted tf32 bits. Warp w: rows (w%4)*16, cols (w/4)*64.
// Epilogue: C -> smem -> fused h-store + alpha + 8-lane butterfly.
// ----------------------------------------------------------------------------
__global__ __launch_bounds__(256) void gemm_tf32_alpha_kernel(
    const float* __restrict__ x, const unsigned int* __restrict__ wt,
    const float* __restrict__ a_s, const float* __restrict__ a_d,
    float* __restrict__ h, float* __restrict__ out_s, float* __restrict__ out_d) {
    extern __shared__ unsigned int smem_u[];
    unsigned int* Xs = smem_u;                       // 64 x XS_STRIDE (reused as hs)
    unsigned int* Wsm = smem_u + 64 * XS_STRIDE;     // 128 x WS_STRIDE
    int t = threadIdx.x;
    int row0 = blockIdx.x * 64;

    // stage X tile (tf32 convert on the fly)
    const float4* x4 = reinterpret_cast<const float4*>(x);
#pragma unroll
    for (int i = 0; i < 8; i++) {
        int idx = t + i * 256;          // 2048 float4 slots (64 rows x 32)
        int r = idx >> 5, c4 = idx & 31;
        float4 v = make_float4(0.f, 0.f, 0.f, 0.f);
        if (row0 + r < N_NODES) v = x4[(size_t)(row0 + r) * 32 + c4];
        uint4 u = make_uint4(f2tf32(v.x), f2tf32(v.y), f2tf32(v.z), f2tf32(v.w));
        *reinterpret_cast<uint4*>(Xs + r * XS_STRIDE + c4 * 4) = u;
    }
    // stage W (pure uint4 copy of pre-converted bits)
    const uint4* wt4 = reinterpret_cast<const uint4*>(wt);
#pragma unroll
    for (int i = 0; i < 16; i++) {
        int idx = t + i * 256;          // 4096 uint4 slots (128 rows x 32)
        int r = idx >> 5, c4 = idx & 31;
        *reinterpret_cast<uint4*>(Wsm + r * WS_STRIDE + c4 * 4) = wt4[r * 32 + c4];
    }
    __syncthreads();

    int warp = t >> 5, lane = t & 31;
    int gid = lane >> 2, tid4 = lane & 3;
    int r0 = (warp & 3) * 16;
    int j0 = (warp >> 2) * 64;

    float c[8][4];
#pragma unroll
    for (int nt = 0; nt < 8; nt++)
#pragma unroll
        for (int j = 0; j < 4; j++) c[nt][j] = 0.f;

#pragma unroll 2
    for (int k0 = 0; k0 < F; k0 += 8) {
        unsigned int a0 = Xs[(r0 + gid) * XS_STRIDE + k0 + tid4];
        unsigned int a1 = Xs[(r0 + gid + 8) * XS_STRIDE + k0 + tid4];
        unsigned int a2 = Xs[(r0 + gid) * XS_STRIDE + k0 + 4 + tid4];
        unsigned int a3 = Xs[(r0 + gid + 8) * XS_STRIDE + k0 + 4 + tid4];
#pragma unroll
        for (int nt = 0; nt < 8; nt++) {
            int jb = j0 + nt * 8;
            unsigned int b0 = Wsm[(k0 + tid4) * WS_STRIDE + jb + gid];
            unsigned int b1 = Wsm[(k0 + tid4 + 4) * WS_STRIDE + jb + gid];
            mma_tf32(c[nt], a0, a1, a2, a3, b0, b1);
        }
    }
    __syncthreads();

    // C frags -> smem (reuse Xs region as float hs[64][XS_STRIDE])
    float* hs = reinterpret_cast<float*>(smem_u);
#pragma unroll
    for (int nt = 0; nt < 8; nt++) {
        int jb = j0 + nt * 8 + tid4 * 2;
        *reinterpret_cast<float2*>(hs + (r0 + gid) * XS_STRIDE + jb) =
            make_float2(c[nt][0], c[nt][1]);
        *reinterpret_cast<float2*>(hs + (r0 + gid + 8) * XS_STRIDE + jb) =
            make_float2(c[nt][2], c[nt][3]);
    }
    __syncthreads();

    // fused h store + alpha
    int t_row = t >> 5, t_col = t & 31;
    float4 asv = reinterpret_cast<const float4*>(a_s)[t_col];
    float4 adv = reinterpret_cast<const float4*>(a_d)[t_col];
    int head = t_col >> 3;
    float4* h4 = reinterpret_cast<float4*>(h);
#pragma unroll
    for (int r = 0; r < 8; r++) {
        int row = row0 + t_row * 8 + r;
        float4 hv = *reinterpret_cast<float4*>(hs + (t_row * 8 + r) * XS_STRIDE + t_col * 4);
        if (row < N_NODES)
            h4[(size_t)row * 32 + t_col] = hv;
        float ps = hv.x * asv.x + hv.y * asv.y + hv.z * asv.z + hv.w * asv.w;
        float pd = hv.x * adv.x + hv.y * adv.y + hv.z * adv.z + hv.w * adv.w;
#pragma unroll
        for (int o = 1; o < 8; o <<= 1) {
            ps += __shfl_xor_sync(0xffffffffu, ps, o);
            pd += __shfl_xor_sync(0xffffffffu, pd, o);
        }
        if ((t_col & 7) == 0 && row < N_NODES) {
            out_s[row * HEADS + head] = ps;
            out_d[row * HEADS + head] = pd;
        }
    }
}

// ----------------------------------------------------------------------------
// Fused softmax + aggregation: one warp per dst node, unroll x8 (8 independent
// csr->as->h chains in flight). lane covers channels 4*lane..4*lane+3;
// head = lane>>3; q identical across the 8 lanes of a head -> no reduction.
// ----------------------------------------------------------------------------
__global__ __launch_bounds__(256) void agg_fused_kernel(
    const float* __restrict__ h, const int* __restrict__ off,
    const int* __restrict__ csr, const float* __restrict__ as,
    const float* __restrict__ ad, const float* __restrict__ bias,
    float* __restrict__ out) {
    int warp = threadIdx.x >> 5;
    int lane = threadIdx.x & 31;
    int n = blockIdx.x * 8 + warp;
    if (n >= N_NODES) return;

    int head = lane >> 3;
    float ad_h = ad[n * HEADS + head];
    const float4* h4 = reinterpret_cast<const float4*>(h);

    float4 acc = make_float4(0.f, 0.f, 0.f, 0.f);
    float den = 0.f;
    int s0 = off[n], s1 = off[n + 1];

    int pos = s0;
    for (; pos + 8 <= s1; pos += 8) {
        int sa0 = csr[pos];     int sa1 = csr[pos + 1];
        int sa2 = csr[pos + 2]; int sa3 = csr[pos + 3];
        int sa4 = csr[pos + 4]; int sa5 = csr[pos + 5];
        int sa6 = csr[pos + 6]; int sa7 = csr[pos + 7];
        float e0 = as[sa0 * HEADS + head] + ad_h;
        float e1 = as[sa1 * HEADS + head] + ad_h;
        float e2 = as[sa2 * HEADS + head] + ad_h;
        float e3 = as[sa3 * HEADS + head] + ad_h;
        float e4 = as[sa4 * HEADS + head] + ad_h;
        float e5 = as[sa5 * HEADS + head] + ad_h;
        float e6 = as[sa6 * HEADS + head] + ad_h;
        float e7 = as[sa7 * HEADS + head] + ad_h;
        e0 = e0 > 0.f ? e0 : NEG_SLOPE * e0;
        e1 = e1 > 0.f ? e1 : NEG_SLOPE * e1;
        e2 = e2 > 0.f ? e2 : NEG_SLOPE * e2;
        e3 = e3 > 0.f ? e3 : NEG_SLOPE * e3;
        e4 = e4 > 0.f ? e4 : NEG_SLOPE * e4;
        e5 = e5 > 0.f ? e5 : NEG_SLOPE * e5;
        e6 = e6 > 0.f ? e6 : NEG_SLOPE * e6;
        e7 = e7 > 0.f ? e7 : NEG_SLOPE * e7;
        float q0 = __expf(e0), q1 = __expf(e1), q2 = __expf(e2), q3 = __expf(e3);
        float q4 = __expf(e4), q5 = __expf(e5), q6 = __expf(e6), q7 = __expf(e7);
        float4 h0 = h4[(size_t)sa0 * 32 + lane];
        float4 h1 = h4[(size_t)sa1 * 32 + lane];
        float4 h2 = h4[(size_t)sa2 * 32 + lane];
        float4 h3 = h4[(size_t)sa3 * 32 + lane];
        float4 h5 = h4[(size_t)sa4 * 32 + lane];
        float4 h6 = h4[(size_t)sa5 * 32 + lane];
        float4 h7 = h4[(size_t)sa6 * 32 + lane];
        float4 h8 = h4[(size_t)sa7 * 32 + lane];
        acc.x += q0 * h0.x + q1 * h1.x + q2 * h2.x + q3 * h3.x;
        acc.y += q0 * h0.y + q1 * h1.y + q2 * h2.y + q3 * h3.y;
        acc.z += q0 * h0.z + q1 * h1.z + q2 * h2.z + q3 * h3.z;
        acc.w += q0 * h0.w + q1 * h1.w + q2 * h2.w + q3 * h3.w;
        acc.x += q4 * h5.x + q5 * h6.x + q6 * h7.x + q7 * h8.x;
        acc.y += q4 * h5.y + q5 * h6.y + q6 * h7.y + q7 * h8.y;
        acc.z += q4 * h5.z + q5 * h6.z + q6 * h7.z + q7 * h8.z;
        acc.w += q4 * h5.w + q5 * h6.w + q6 * h7.w + q7 * h8.w;
        den += ((q0 + q1) + (q2 + q3)) + ((q4 + q5) + (q6 + q7));
    }
    for (; pos < s1; pos++) {
        int sa = csr[pos];
        float e = as[sa * HEADS + head] + ad_h;
        e = e > 0.f ? e : NEG_SLOPE * e;
        float q = __expf(e);
        float4 ha = h4[(size_t)sa * 32 + lane];
        acc.x += q * ha.x; acc.y += q * ha.y;
        acc.z += q * ha.z; acc.w += q * ha.w;
        den += q;
    }

    float inv = 1.f / den;   // deg >= 1 (self loop), den > 0
    float4 bv = reinterpret_cast<const float4*>(bias)[lane];
    float4 o;
    o.x = fmaxf(acc.x * inv + bv.x, 0.f);
    o.y = fmaxf(acc.y * inv + bv.y, 0.f);
    o.z = fmaxf(acc.z * inv + bv.z, 0.f);
    o.w = fmaxf(acc.w * inv + bv.w, 0.f);
    reinterpret_cast<float4*>(out)[(size_t)n * 32 + lane] = o;
}

// ----------------------------------------------------------------------------
// Launch
// ----------------------------------------------------------------------------
extern "C" void kernel_launch(void* const* d_in, const int* in_sizes, int n_in,
                              void* d_out, int out_size) {
    const float* x    = (const float*)d_in[0];
    const int*   ei   = (const int*)d_in[1];
    const float* Ws   = (const float*)d_in[2];
    const float* a_s  = (const float*)d_in[3];
    const float* a_d  = (const float*)d_in[4];
    const float* bias = (const float*)d_in[5];
    float*       out  = (float*)d_out;

    void* pv;
    cudaGetSymbolAddress(&pv, g_x0);  float* x0  = (float*)pv;
    cudaGetSymbolAddress(&pv, g_x1);  float* x1  = (float*)pv;
    cudaGetSymbolAddress(&pv, g_h);   float* h   = (float*)pv;
    cudaGetSymbolAddress(&pv, g_as);  float* as  = (float*)pv;
    cudaGetSymbolAddress(&pv, g_ad);  float* ad  = (float*)pv;
    cudaGetSymbolAddress(&pv, g_wt);  unsigned int* wt = (unsigned int*)pv;
    cudaGetSymbolAddress(&pv, g_deg); int*   deg = (int*)pv;
    cudaGetSymbolAddress(&pv, g_off); int*   off = (int*)pv;
    cudaGetSymbolAddress(&pv, g_cur); int*   cur = (int*)pv;
    cudaGetSymbolAddress(&pv, g_csr); int*   csr = (int*)pv;

    cudaFuncSetAttribute(gemm_tf32_alpha_kernel,
                         cudaFuncAttributeMaxDynamicSharedMemorySize, GEMM_SMEM);
    cudaFuncSetAttribute(gemm_tf32_alpha_kernel,
                         cudaFuncAttributePreferredSharedMemoryCarveout, 100);

    // W pre-convert + CSR build (once; reused by all 3 layers)
    wconv_kernel<<<(3 * F * F + 255) / 256, 256>>>(Ws, wt);
    deg_one_kernel<<<(N_NODES + 255) / 256, 256>>>(deg);
    hist_kernel<<<(N_EDGES / 4 + 255) / 256, 256>>>(ei, deg);
    scan_kernel<<<1, 1024>>>(deg, off, cur);
    fill_kernel<<<(E_TOT / 4 + 255) / 256, 256>>>(ei, cur, csr);

    for (int l = 0; l < 3; l++) {
        const float* xin = (l == 0) ? x : ((l == 1) ? x0 : x1);
        float* xout = (l == 0) ? x0 : ((l == 1) ? x1 : out);
        gemm_tf32_alpha_kernel<<<(N_NODES + 63) / 64, 256, GEMM_SMEM>>>(
            xin, wt + (size_t)l * F * F, a_s + l * F, a_d + l * F, h, as, ad);
        agg_fused_kernel<<<(N_NODES + 7) / 8, 256>>>(
            h, off, csr, as, ad, bias + l * F, xout);
    }
}

// round 14
// speedup vs baseline: 1.3790x; 1.3030x over previous
#include <cuda_runtime.h>
#include <cuda_bf16.h>
#include <math.h>

#define N_NODES 50000
#define N_EDGES 800000
#define E_TOT   (N_EDGES + N_NODES)   // edges + self loops = 850000
#define F       128                   // in/out feature dim
#define HEADS   4
#define HDIM    32
#define NEG_SLOPE 0.2f

// GEMM smem layout (tf32 staging, padded for conflict-free fragment LDS)
#define XS_STRIDE 132                 // 64 x 132 uint  (33792 B)
#define WS_STRIDE 136                 // 128 x 136 uint (69632 B)
#define GEMM_SMEM (64 * XS_STRIDE * 4 + 128 * WS_STRIDE * 4)   // 103424 B

// scan decomposition
#define SB 256
#define NB ((N_NODES + SB - 1) / SB)  // 196

// ----------------------------------------------------------------------------
// Scratch (device globals; no allocation allowed)
// ----------------------------------------------------------------------------
__device__ float        g_x0[N_NODES * F];      // layer ping buffer
__device__ float        g_x1[N_NODES * F];      // layer pong buffer
__device__ float        g_h [N_NODES * F];      // h = x @ W (fp32)
__device__ float        g_as[N_NODES * HEADS];  // alpha_src per node
__device__ float        g_ad[N_NODES * HEADS];  // alpha_dst per node
__device__ unsigned int g_wt[3 * F * F];        // pre-converted tf32 weights
__device__ int          g_deg[N_NODES];
__device__ int          g_off[N_NODES + 1];
__device__ int          g_cur[N_NODES];
__device__ int          g_part[NB];
__device__ int          g_poff[NB];
__device__ int          g_csr[E_TOT];           // src node per CSR slot

// ----------------------------------------------------------------------------
// tf32 / mma helpers
// ----------------------------------------------------------------------------
__device__ __forceinline__ unsigned int f2tf32(float f) {
    unsigned int u;
    asm("cvt.rna.tf32.f32 %0, %1;" : "=r"(u) : "f"(f));
    return u;
}
__device__ __forceinline__ void mma_tf32(float* c,
    unsigned int a0, unsigned int a1, unsigned int a2, unsigned int a3,
    unsigned int b0, unsigned int b1) {
    asm("mma.sync.aligned.m16n8k8.row.col.f32.tf32.tf32.f32 "
        "{%0,%1,%2,%3}, {%4,%5,%6,%7}, {%8,%9}, {%0,%1,%2,%3};"
        : "+f"(c[0]), "+f"(c[1]), "+f"(c[2]), "+f"(c[3])
        : "r"(a0), "r"(a1), "r"(a2), "r"(a3), "r"(b0), "r"(b1));
}

// ----------------------------------------------------------------------------
// W pre-convert: all 3 layers' weights -> tf32 bits (once per launch)
// ----------------------------------------------------------------------------
__global__ void wconv_kernel(const float* __restrict__ Ws,
                             unsigned int* __restrict__ wt) {
    int i = blockIdx.x * blockDim.x + threadIdx.x;
    if (i < 3 * F * F) wt[i] = f2tf32(Ws[i]);
}

// ----------------------------------------------------------------------------
// CSR construction (edge_index is int32).
// deg starts at 1 (self loop folded in); hist covers real edges only, int4.
// ----------------------------------------------------------------------------
__global__ void deg_one_kernel(int* __restrict__ deg) {
    int i = blockIdx.x * blockDim.x + threadIdx.x;
    if (i < N_NODES) deg[i] = 1;
}

__global__ void hist_kernel(const int* __restrict__ ei, int* __restrict__ deg) {
    int i = blockIdx.x * blockDim.x + threadIdx.x;
    if (i >= N_EDGES / 4) return;
    int4 d4 = reinterpret_cast<const int4*>(ei + N_EDGES)[i];
    if (d4.x >= 0 && d4.x < N_NODES) atomicAdd(&deg[d4.x], 1);
    if (d4.y >= 0 && d4.y < N_NODES) atomicAdd(&deg[d4.y], 1);
    if (d4.z >= 0 && d4.z < N_NODES) atomicAdd(&deg[d4.z], 1);
    if (d4.w >= 0 && d4.w < N_NODES) atomicAdd(&deg[d4.w], 1);
}

// ----------------------------------------------------------------------------
// Device-wide exclusive scan of deg, 3 parallel phases
// ----------------------------------------------------------------------------
__global__ void partial_kernel(const int* __restrict__ deg,
                               int* __restrict__ part) {
    __shared__ int s[SB];
    int b = blockIdx.x, t = threadIdx.x;
    int i = b * SB + t;
    s[t] = (i < N_NODES) ? deg[i] : 0;
    __syncthreads();
#pragma unroll
    for (int o = SB / 2; o > 0; o >>= 1) {
        if (t < o) s[t] += s[t + o];
        __syncthreads();
    }
    if (t == 0) part[b] = s[0];
}

__global__ void scan_parts_kernel(const int* __restrict__ part,
                                  int* __restrict__ poff,
                                  int* __restrict__ off) {
    __shared__ int s[256];
    int t = threadIdx.x;
    int v = (t < NB) ? part[t] : 0;
    s[t] = v;
    __syncthreads();
#pragma unroll
    for (int o = 1; o < 256; o <<= 1) {
        int u = (t >= o) ? s[t - o] : 0;
        __syncthreads();
        s[t] += u;
        __syncthreads();
    }
    if (t < NB) poff[t] = s[t] - v;         // exclusive block offset
    if (t == 255) off[N_NODES] = s[255];    // grand total (= E_TOT)
}

__global__ void offsets_kernel(const int* __restrict__ deg,
                               const int* __restrict__ poff,
                               int* __restrict__ off, int* __restrict__ cur) {
    __shared__ int s[SB];
    int b = blockIdx.x, t = threadIdx.x;
    int i = b * SB + t;
    int v = (i < N_NODES) ? deg[i] : 0;
    s[t] = v;
    __syncthreads();
#pragma unroll
    for (int o = 1; o < SB; o <<= 1) {
        int u = (t >= o) ? s[t - o] : 0;
        __syncthreads();
        s[t] += u;
        __syncthreads();
    }
    if (i < N_NODES) {
        int e = poff[b] + s[t] - v;         // exclusive
        off[i] = e;
        cur[i] = e;
    }
}

__device__ __forceinline__ void fill_one(int src, int dst,
                                         int* __restrict__ cur,
                                         int* __restrict__ csr) {
    if (dst < 0 || dst >= N_NODES) return;
    if (src < 0) src = 0; if (src >= N_NODES) src = N_NODES - 1;
    int pos = atomicAdd(&cur[dst], 1);
    csr[pos] = src;
}

__global__ void fill_kernel(const int* __restrict__ ei, int* __restrict__ cur,
                            int* __restrict__ csr) {
    int i = blockIdx.x * blockDim.x + threadIdx.x;
    if (i < N_EDGES / 4) {
        int4 s4 = reinterpret_cast<const int4*>(ei)[i];
        int4 d4 = reinterpret_cast<const int4*>(ei + N_EDGES)[i];
        fill_one(s4.x, d4.x, cur, csr);
        fill_one(s4.y, d4.y, cur, csr);
        fill_one(s4.z, d4.z, cur, csr);
        fill_one(s4.w, d4.w, cur, csr);
    } else if (i < E_TOT / 4) {
        int node = i * 4 - N_EDGES;
#pragma unroll
        for (int j = 0; j < 4; j++) {
            int pos = atomicAdd(&cur[node + j], 1);
            csr[pos] = node + j;
        }
    }
}

// ----------------------------------------------------------------------------
// tf32 tensor-core GEMM + alpha fusion (64x128 tile per block).
// W staged from pre-converted tf32 bits. Warp w: rows (w%4)*16, cols (w/4)*64.
// Epilogue: C -> smem -> fused h-store + alpha + 8-lane butterfly.
// ----------------------------------------------------------------------------
__global__ __launch_bounds__(256) void gemm_tf32_alpha_kernel(
    const float* __restrict__ x, const unsigned int* __restrict__ wt,
    const float* __restrict__ a_s, const float* __restrict__ a_d,
    float* __restrict__ h, float* __restrict__ out_s, float* __restrict__ out_d) {
    extern __shared__ unsigned int smem_u[];
    unsigned int* Xs = smem_u;                       // 64 x XS_STRIDE (reused as hs)
    unsigned int* Wsm = smem_u + 64 * XS_STRIDE;     // 128 x WS_STRIDE
    int t = threadIdx.x;
    int row0 = blockIdx.x * 64;

    // stage X tile (tf32 convert on the fly)
    const float4* x4 = reinterpret_cast<const float4*>(x);
#pragma unroll
    for (int i = 0; i < 8; i++) {
        int idx = t + i * 256;          // 2048 float4 slots (64 rows x 32)
        int r = idx >> 5, c4 = idx & 31;
        float4 v = make_float4(0.f, 0.f, 0.f, 0.f);
        if (row0 + r < N_NODES) v = x4[(size_t)(row0 + r) * 32 + c4];
        uint4 u = make_uint4(f2tf32(v.x), f2tf32(v.y), f2tf32(v.z), f2tf32(v.w));
        *reinterpret_cast<uint4*>(Xs + r * XS_STRIDE + c4 * 4) = u;
    }
    // stage W (pure uint4 copy of pre-converted bits)
    const uint4* wt4 = reinterpret_cast<const uint4*>(wt);
#pragma unroll
    for (int i = 0; i < 16; i++) {
        int idx = t + i * 256;          // 4096 uint4 slots (128 rows x 32)
        int r = idx >> 5, c4 = idx & 31;
        *reinterpret_cast<uint4*>(Wsm + r * WS_STRIDE + c4 * 4) = wt4[r * 32 + c4];
    }
    __syncthreads();

    int warp = t >> 5, lane = t & 31;
    int gid = lane >> 2, tid4 = lane & 3;
    int r0 = (warp & 3) * 16;
    int j0 = (warp >> 2) * 64;

    float c[8][4];
#pragma unroll
    for (int nt = 0; nt < 8; nt++)
#pragma unroll
        for (int j = 0; j < 4; j++) c[nt][j] = 0.f;

#pragma unroll 2
    for (int k0 = 0; k0 < F; k0 += 8) {
        unsigned int a0 = Xs[(r0 + gid) * XS_STRIDE + k0 + tid4];
        unsigned int a1 = Xs[(r0 + gid + 8) * XS_STRIDE + k0 + tid4];
        unsigned int a2 = Xs[(r0 + gid) * XS_STRIDE + k0 + 4 + tid4];
        unsigned int a3 = Xs[(r0 + gid + 8) * XS_STRIDE + k0 + 4 + tid4];
#pragma unroll
        for (int nt = 0; nt < 8; nt++) {
            int jb = j0 + nt * 8;
            unsigned int b0 = Wsm[(k0 + tid4) * WS_STRIDE + jb + gid];
            unsigned int b1 = Wsm[(k0 + tid4 + 4) * WS_STRIDE + jb + gid];
            mma_tf32(c[nt], a0, a1, a2, a3, b0, b1);
        }
    }
    __syncthreads();

    // C frags -> smem (reuse Xs region as float hs[64][XS_STRIDE])
    float* hs = reinterpret_cast<float*>(smem_u);
#pragma unroll
    for (int nt = 0; nt < 8; nt++) {
        int jb = j0 + nt * 8 + tid4 * 2;
        *reinterpret_cast<float2*>(hs + (r0 + gid) * XS_STRIDE + jb) =
            make_float2(c[nt][0], c[nt][1]);
        *reinterpret_cast<float2*>(hs + (r0 + gid + 8) * XS_STRIDE + jb) =
            make_float2(c[nt][2], c[nt][3]);
    }
    __syncthreads();

    // fused h store + alpha
    int t_row = t >> 5, t_col = t & 31;
    float4 asv = reinterpret_cast<const float4*>(a_s)[t_col];
    float4 adv = reinterpret_cast<const float4*>(a_d)[t_col];
    int head = t_col >> 3;
    float4* h4 = reinterpret_cast<float4*>(h);
#pragma unroll
    for (int r = 0; r < 8; r++) {
        int row = row0 + t_row * 8 + r;
        float4 hv = *reinterpret_cast<float4*>(hs + (t_row * 8 + r) * XS_STRIDE + t_col * 4);
        if (row < N_NODES)
            h4[(size_t)row * 32 + t_col] = hv;
        float ps = hv.x * asv.x + hv.y * asv.y + hv.z * asv.z + hv.w * asv.w;
        float pd = hv.x * adv.x + hv.y * adv.y + hv.z * adv.z + hv.w * adv.w;
#pragma unroll
        for (int o = 1; o < 8; o <<= 1) {
            ps += __shfl_xor_sync(0xffffffffu, ps, o);
            pd += __shfl_xor_sync(0xffffffffu, pd, o);
        }
        if ((t_col & 7) == 0 && row < N_NODES) {
            out_s[row * HEADS + head] = ps;
            out_d[row * HEADS + head] = pd;
        }
    }
}

// ----------------------------------------------------------------------------
// Fused softmax + aggregation: one warp per dst node, unroll x8.
// lane covers channels 4*lane..4*lane+3; head = lane>>3; q identical across
// the 8 lanes of a head -> den needs no reduction.
// ----------------------------------------------------------------------------
__global__ __launch_bounds__(256) void agg_fused_kernel(
    const float* __restrict__ h, const int* __restrict__ off,
    const int* __restrict__ csr, const float* __restrict__ as,
    const float* __restrict__ ad, const float* __restrict__ bias,
    float* __restrict__ out) {
    int warp = threadIdx.x >> 5;
    int lane = threadIdx.x & 31;
    int n = blockIdx.x * 8 + warp;
    if (n >= N_NODES) return;

    int head = lane >> 3;
    float ad_h = ad[n * HEADS + head];
    const float4* h4 = reinterpret_cast<const float4*>(h);

    float4 acc = make_float4(0.f, 0.f, 0.f, 0.f);
    float den = 0.f;
    int s0 = off[n], s1 = off[n + 1];

    int pos = s0;
    for (; pos + 8 <= s1; pos += 8) {
        int sa0 = csr[pos];     int sa1 = csr[pos + 1];
        int sa2 = csr[pos + 2]; int sa3 = csr[pos + 3];
        int sa4 = csr[pos + 4]; int sa5 = csr[pos + 5];
        int sa6 = csr[pos + 6]; int sa7 = csr[pos + 7];
        float e0 = as[sa0 * HEADS + head] + ad_h;
        float e1 = as[sa1 * HEADS + head] + ad_h;
        float e2 = as[sa2 * HEADS + head] + ad_h;
        float e3 = as[sa3 * HEADS + head] + ad_h;
        float e4 = as[sa4 * HEADS + head] + ad_h;
        float e5 = as[sa5 * HEADS + head] + ad_h;
        float e6 = as[sa6 * HEADS + head] + ad_h;
        float e7 = as[sa7 * HEADS + head] + ad_h;
        e0 = e0 > 0.f ? e0 : NEG_SLOPE * e0;
        e1 = e1 > 0.f ? e1 : NEG_SLOPE * e1;
        e2 = e2 > 0.f ? e2 : NEG_SLOPE * e2;
        e3 = e3 > 0.f ? e3 : NEG_SLOPE * e3;
        e4 = e4 > 0.f ? e4 : NEG_SLOPE * e4;
        e5 = e5 > 0.f ? e5 : NEG_SLOPE * e5;
        e6 = e6 > 0.f ? e6 : NEG_SLOPE * e6;
        e7 = e7 > 0.f ? e7 : NEG_SLOPE * e7;
        float q0 = __expf(e0), q1 = __expf(e1), q2 = __expf(e2), q3 = __expf(e3);
        float q4 = __expf(e4), q5 = __expf(e5), q6 = __expf(e6), q7 = __expf(e7);
        float4 h0 = h4[(size_t)sa0 * 32 + lane];
        float4 h1 = h4[(size_t)sa1 * 32 + lane];
        float4 h2 = h4[(size_t)sa2 * 32 + lane];
        float4 h3 = h4[(size_t)sa3 * 32 + lane];
        float4 h5 = h4[(size_t)sa4 * 32 + lane];
        float4 h6 = h4[(size_t)sa5 * 32 + lane];
        float4 h7 = h4[(size_t)sa6 * 32 + lane];
        float4 h8 = h4[(size_t)sa7 * 32 + lane];
        acc.x += q0 * h0.x + q1 * h1.x + q2 * h2.x + q3 * h3.x;
        acc.y += q0 * h0.y + q1 * h1.y + q2 * h2.y + q3 * h3.y;
        acc.z += q0 * h0.z + q1 * h1.z + q2 * h2.z + q3 * h3.z;
        acc.w += q0 * h0.w + q1 * h1.w + q2 * h2.w + q3 * h3.w;
        acc.x += q4 * h5.x + q5 * h6.x + q6 * h7.x + q7 * h8.x;
        acc.y += q4 * h5.y + q5 * h6.y + q6 * h7.y + q7 * h8.y;
        acc.z += q4 * h5.z + q5 * h6.z + q6 * h7.z + q7 * h8.z;
        acc.w += q4 * h5.w + q5 * h6.w + q6 * h7.w + q7 * h8.w;
        den += ((q0 + q1) + (q2 + q3)) + ((q4 + q5) + (q6 + q7));
    }
    for (; pos < s1; pos++) {
        int sa = csr[pos];
        float e = as[sa * HEADS + head] + ad_h;
        e = e > 0.f ? e : NEG_SLOPE * e;
        float q = __expf(e);
        float4 ha = h4[(size_t)sa * 32 + lane];
        acc.x += q * ha.x; acc.y += q * ha.y;
        acc.z += q * ha.z; acc.w += q * ha.w;
        den += q;
    }

    float inv = 1.f / den;   // deg >= 1 (self loop), den > 0
    float4 bv = reinterpret_cast<const float4*>(bias)[lane];
    float4 o;
    o.x = fmaxf(acc.x * inv + bv.x, 0.f);
    o.y = fmaxf(acc.y * inv + bv.y, 0.f);
    o.z = fmaxf(acc.z * inv + bv.z, 0.f);
    o.w = fmaxf(acc.w * inv + bv.w, 0.f);
    reinterpret_cast<float4*>(out)[(size_t)n * 32 + lane] = o;
}

// ----------------------------------------------------------------------------
// Launch
// ----------------------------------------------------------------------------
extern "C" void kernel_launch(void* const* d_in, const int* in_sizes, int n_in,
                              void* d_out, int out_size) {
    const float* x    = (const float*)d_in[0];
    const int*   ei   = (const int*)d_in[1];
    const float* Ws   = (const float*)d_in[2];
    const float* a_s  = (const float*)d_in[3];
    const float* a_d  = (const float*)d_in[4];
    const float* bias = (const float*)d_in[5];
    float*       out  = (float*)d_out;

    void* pv;
    cudaGetSymbolAddress(&pv, g_x0);   float* x0  = (float*)pv;
    cudaGetSymbolAddress(&pv, g_x1);   float* x1  = (float*)pv;
    cudaGetSymbolAddress(&pv, g_h);    float* h   = (float*)pv;
    cudaGetSymbolAddress(&pv, g_as);   float* as  = (float*)pv;
    cudaGetSymbolAddress(&pv, g_ad);   float* ad  = (float*)pv;
    cudaGetSymbolAddress(&pv, g_wt);   unsigned int* wt = (unsigned int*)pv;
    cudaGetSymbolAddress(&pv, g_deg);  int*   deg  = (int*)pv;
    cudaGetSymbolAddress(&pv, g_off);  int*   off  = (int*)pv;
    cudaGetSymbolAddress(&pv, g_cur);  int*   cur  = (int*)pv;
    cudaGetSymbolAddress(&pv, g_part); int*   part = (int*)pv;
    cudaGetSymbolAddress(&pv, g_poff); int*   poff = (int*)pv;
    cudaGetSymbolAddress(&pv, g_csr);  int*   csr  = (int*)pv;

    cudaFuncSetAttribute(gemm_tf32_alpha_kernel,
                         cudaFuncAttributeMaxDynamicSharedMemorySize, GEMM_SMEM);
    cudaFuncSetAttribute(gemm_tf32_alpha_kernel,
                         cudaFuncAttributePreferredSharedMemoryCarveout, 100);

    // W pre-convert + CSR build (once; reused by all 3 layers)
    wconv_kernel<<<(3 * F * F + 255) / 256, 256>>>(Ws, wt);
    deg_one_kernel<<<(N_NODES + 255) / 256, 256>>>(deg);
    hist_kernel<<<(N_EDGES / 4 + 255) / 256, 256>>>(ei, deg);
    partial_kernel<<<NB, SB>>>(deg, part);
    scan_parts_kernel<<<1, 256>>>(part, poff, off);
    offsets_kernel<<<NB, SB>>>(deg, poff, off, cur);
    fill_kernel<<<(E_TOT / 4 + 255) / 256, 256>>>(ei, cur, csr);

    for (int l = 0; l < 3; l++) {
        const float* xin = (l == 0) ? x : ((l == 1) ? x0 : x1);
        float* xout = (l == 0) ? x0 : ((l == 1) ? x1 : out);
        gemm_tf32_alpha_kernel<<<(N_NODES + 63) / 64, 256, GEMM_SMEM>>>(
            xin, wt + (size_t)l * F * F, a_s + l * F, a_d + l * F, h, as, ad);
        agg_fused_kernel<<<(N_NODES + 7) / 8, 256>>>(
            h, off, csr, as, ad, bias + l * F, xout);
    }
}

// round 16
// speedup vs baseline: 1.4206x; 1.0302x over previous
#include <cuda_runtime.h>
#include <cuda_bf16.h>
#include <math.h>

#define N_NODES 50000
#define N_EDGES 800000
#define E_TOT   (N_EDGES + N_NODES)   // edges + self loops = 850000
#define F       128                   // in/out feature dim
#define HEADS   4
#define HDIM    32
#define NEG_SLOPE 0.2f

// GEMM smem layout (tf32 staging, padded for conflict-free fragment LDS)
#define XS_STRIDE 132                 // 64 x 132 uint  (33792 B)
#define WS_STRIDE 136                 // 128 x 136 uint (69632 B)
#define GEMM_SMEM (64 * XS_STRIDE * 4 + 128 * WS_STRIDE * 4)   // 103424 B

// scan decomposition
#define SB 256
#define NB ((N_NODES + SB - 1) / SB)  // 196

// ----------------------------------------------------------------------------
// Scratch (device globals; no allocation allowed)
// ----------------------------------------------------------------------------
__device__ float        g_x0[N_NODES * F];      // layer ping buffer
__device__ float        g_x1[N_NODES * F];      // layer pong buffer
__device__ float        g_h [N_NODES * F];      // h = x @ W (fp32)
__device__ float        g_as[N_NODES * HEADS];  // alpha_src per node
__device__ float        g_ad[N_NODES * HEADS];  // alpha_dst per node
__device__ unsigned int g_wt[3 * F * F];        // pre-converted tf32 weights
__device__ int          g_deg[N_NODES];
__device__ int          g_off[N_NODES + 1];
__device__ int          g_cur[N_NODES];
__device__ int          g_part[NB];
__device__ int          g_poff[NB];
__device__ int          g_csr[E_TOT];           // src node per CSR slot

// ----------------------------------------------------------------------------
// tf32 / mma helpers
// ----------------------------------------------------------------------------
__device__ __forceinline__ unsigned int f2tf32(float f) {
    unsigned int u;
    asm("cvt.rna.tf32.f32 %0, %1;" : "=r"(u) : "f"(f));
    return u;
}
__device__ __forceinline__ void mma_tf32(float* c,
    unsigned int a0, unsigned int a1, unsigned int a2, unsigned int a3,
    unsigned int b0, unsigned int b1) {
    asm("mma.sync.aligned.m16n8k8.row.col.f32.tf32.tf32.f32 "
        "{%0,%1,%2,%3}, {%4,%5,%6,%7}, {%8,%9}, {%0,%1,%2,%3};"
        : "+f"(c[0]), "+f"(c[1]), "+f"(c[2]), "+f"(c[3])
        : "r"(a0), "r"(a1), "r"(a2), "r"(a3), "r"(b0), "r"(b1));
}

// ----------------------------------------------------------------------------
// W pre-convert: all 3 layers' weights -> tf32 bits (once per launch)
// ----------------------------------------------------------------------------
__global__ void wconv_kernel(const float* __restrict__ Ws,
                             unsigned int* __restrict__ wt) {
    int i = blockIdx.x * blockDim.x + threadIdx.x;
    if (i < 3 * F * F) wt[i] = f2tf32(Ws[i]);
}

// ----------------------------------------------------------------------------
// CSR construction (edge_index is int32).
// deg starts at 1 (self loop folded in); hist covers real edges only, int4.
// ----------------------------------------------------------------------------
__global__ void deg_one_kernel(int* __restrict__ deg) {
    int i = blockIdx.x * blockDim.x + threadIdx.x;
    if (i < N_NODES) deg[i] = 1;
}

__global__ void hist_kernel(const int* __restrict__ ei, int* __restrict__ deg) {
    int i = blockIdx.x * blockDim.x + threadIdx.x;
    if (i >= N_EDGES / 4) return;
    int4 d4 = reinterpret_cast<const int4*>(ei + N_EDGES)[i];
    if (d4.x >= 0 && d4.x < N_NODES) atomicAdd(&deg[d4.x], 1);
    if (d4.y >= 0 && d4.y < N_NODES) atomicAdd(&deg[d4.y], 1);
    if (d4.z >= 0 && d4.z < N_NODES) atomicAdd(&deg[d4.z], 1);
    if (d4.w >= 0 && d4.w < N_NODES) atomicAdd(&deg[d4.w], 1);
}

// ----------------------------------------------------------------------------
// Device-wide exclusive scan of deg, 3 parallel phases
// ----------------------------------------------------------------------------
__global__ void partial_kernel(const int* __restrict__ deg,
                               int* __restrict__ part) {
    __shared__ int s[SB];
    int b = blockIdx.x, t = threadIdx.x;
    int i = b * SB + t;
    s[t] = (i < N_NODES) ? deg[i] : 0;
    __syncthreads();
#pragma unroll
    for (int o = SB / 2; o > 0; o >>= 1) {
        if (t < o) s[t] += s[t + o];
        __syncthreads();
    }
    if (t == 0) part[b] = s[0];
}

__global__ void scan_parts_kernel(const int* __restrict__ part,
                                  int* __restrict__ poff,
                                  int* __restrict__ off) {
    __shared__ int s[256];
    int t = threadIdx.x;
    int v = (t < NB) ? part[t] : 0;
    s[t] = v;
    __syncthreads();
#pragma unroll
    for (int o = 1; o < 256; o <<= 1) {
        int u = (t >= o) ? s[t - o] : 0;
        __syncthreads();
        s[t] += u;
        __syncthreads();
    }
    if (t < NB) poff[t] = s[t] - v;         // exclusive block offset
    if (t == 255) off[N_NODES] = s[255];    // grand total (= E_TOT)
}

__global__ void offsets_kernel(const int* __restrict__ deg,
                               const int* __restrict__ poff,
                               int* __restrict__ off, int* __restrict__ cur) {
    __shared__ int s[SB];
    int b = blockIdx.x, t = threadIdx.x;
    int i = b * SB + t;
    int v = (i < N_NODES) ? deg[i] : 0;
    s[t] = v;
    __syncthreads();
#pragma unroll
    for (int o = 1; o < SB; o <<= 1) {
        int u = (t >= o) ? s[t - o] : 0;
        __syncthreads();
        s[t] += u;
        __syncthreads();
    }
    if (i < N_NODES) {
        int e = poff[b] + s[t] - v;         // exclusive
        off[i] = e;
        cur[i] = e;
    }
}

__device__ __forceinline__ void fill_one(int src, int dst,
                                         int* __restrict__ cur,
                                         int* __restrict__ csr) {
    if (dst < 0 || dst >= N_NODES) return;
    if (src < 0) src = 0; if (src >= N_NODES) src = N_NODES - 1;
    int pos = atomicAdd(&cur[dst], 1);
    csr[pos] = src;
}

__global__ void fill_kernel(const int* __restrict__ ei, int* __restrict__ cur,
                            int* __restrict__ csr) {
    int i = blockIdx.x * blockDim.x + threadIdx.x;
    if (i < N_EDGES / 4) {
        int4 s4 = reinterpret_cast<const int4*>(ei)[i];
        int4 d4 = reinterpret_cast<const int4*>(ei + N_EDGES)[i];
        fill_one(s4.x, d4.x, cur, csr);
        fill_one(s4.y, d4.y, cur, csr);
        fill_one(s4.z, d4.z, cur, csr);
        fill_one(s4.w, d4.w, cur, csr);
    } else if (i < E_TOT / 4) {
        int node = i * 4 - N_EDGES;
#pragma unroll
        for (int j = 0; j < 4; j++) {
            int pos = atomicAdd(&cur[node + j], 1);
            csr[pos] = node + j;
        }
    }
}

// ----------------------------------------------------------------------------
// tf32 tensor-core GEMM + alpha fusion (64x128 tile per block).
// W staged from pre-converted tf32 bits. Warp w: rows (w%4)*16, cols (w/4)*64.
// Epilogue: C -> smem -> fused h-store + alpha + 8-lane butterfly.
// ----------------------------------------------------------------------------
__global__ __launch_bounds__(256) void gemm_tf32_alpha_kernel(
    const float* __restrict__ x, const unsigned int* __restrict__ wt,
    const float* __restrict__ a_s, const float* __restrict__ a_d,
    float* __restrict__ h, float* __restrict__ out_s, float* __restrict__ out_d) {
    extern __shared__ unsigned int smem_u[];
    unsigned int* Xs = smem_u;                       // 64 x XS_STRIDE (reused as hs)
    unsigned int* Wsm = smem_u + 64 * XS_STRIDE;     // 128 x WS_STRIDE
    int t = threadIdx.x;
    int row0 = blockIdx.x * 64;

    // stage X tile (tf32 convert on the fly)
    const float4* x4 = reinterpret_cast<const float4*>(x);
#pragma unroll
    for (int i = 0; i < 8; i++) {
        int idx = t + i * 256;          // 2048 float4 slots (64 rows x 32)
        int r = idx >> 5, c4 = idx & 31;
        float4 v = make_float4(0.f, 0.f, 0.f, 0.f);
        if (row0 + r < N_NODES) v = x4[(size_t)(row0 + r) * 32 + c4];
        uint4 u = make_uint4(f2tf32(v.x), f2tf32(v.y), f2tf32(v.z), f2tf32(v.w));
        *reinterpret_cast<uint4*>(Xs + r * XS_STRIDE + c4 * 4) = u;
    }
    // stage W (pure uint4 copy of pre-converted bits)
    const uint4* wt4 = reinterpret_cast<const uint4*>(wt);
#pragma unroll
    for (int i = 0; i < 16; i++) {
        int idx = t + i * 256;          // 4096 uint4 slots (128 rows x 32)
        int r = idx >> 5, c4 = idx & 31;
        *reinterpret_cast<uint4*>(Wsm + r * WS_STRIDE + c4 * 4) = wt4[r * 32 + c4];
    }
    __syncthreads();

    int warp = t >> 5, lane = t & 31;
    int gid = lane >> 2, tid4 = lane & 3;
    int r0 = (warp & 3) * 16;
    int j0 = (warp >> 2) * 64;

    float c[8][4];
#pragma unroll
    for (int nt = 0; nt < 8; nt++)
#pragma unroll
        for (int j = 0; j < 4; j++) c[nt][j] = 0.f;

#pragma unroll 2
    for (int k0 = 0; k0 < F; k0 += 8) {
        unsigned int a0 = Xs[(r0 + gid) * XS_STRIDE + k0 + tid4];
        unsigned int a1 = Xs[(r0 + gid + 8) * XS_STRIDE + k0 + tid4];
        unsigned int a2 = Xs[(r0 + gid) * XS_STRIDE + k0 + 4 + tid4];
        unsigned int a3 = Xs[(r0 + gid + 8) * XS_STRIDE + k0 + 4 + tid4];
#pragma unroll
        for (int nt = 0; nt < 8; nt++) {
            int jb = j0 + nt * 8;
            unsigned int b0 = Wsm[(k0 + tid4) * WS_STRIDE + jb + gid];
            unsigned int b1 = Wsm[(k0 + tid4 + 4) * WS_STRIDE + jb + gid];
            mma_tf32(c[nt], a0, a1, a2, a3, b0, b1);
        }
    }
    __syncthreads();

    // C frags -> smem (reuse Xs region as float hs[64][XS_STRIDE])
    float* hs = reinterpret_cast<float*>(smem_u);
#pragma unroll
    for (int nt = 0; nt < 8; nt++) {
        int jb = j0 + nt * 8 + tid4 * 2;
        *reinterpret_cast<float2*>(hs + (r0 + gid) * XS_STRIDE + jb) =
            make_float2(c[nt][0], c[nt][1]);
        *reinterpret_cast<float2*>(hs + (r0 + gid + 8) * XS_STRIDE + jb) =
            make_float2(c[nt][2], c[nt][3]);
    }
    __syncthreads();

    // fused h store + alpha
    int t_row = t >> 5, t_col = t & 31;
    float4 asv = reinterpret_cast<const float4*>(a_s)[t_col];
    float4 adv = reinterpret_cast<const float4*>(a_d)[t_col];
    int head = t_col >> 3;
    float4* h4 = reinterpret_cast<float4*>(h);
#pragma unroll
    for (int r = 0; r < 8; r++) {
        int row = row0 + t_row * 8 + r;
        float4 hv = *reinterpret_cast<float4*>(hs + (t_row * 8 + r) * XS_STRIDE + t_col * 4);
        if (row < N_NODES)
            h4[(size_t)row * 32 + t_col] = hv;
        float ps = hv.x * asv.x + hv.y * asv.y + hv.z * asv.z + hv.w * asv.w;
        float pd = hv.x * adv.x + hv.y * adv.y + hv.z * adv.z + hv.w * adv.w;
#pragma unroll
        for (int o = 1; o < 8; o <<= 1) {
            ps += __shfl_xor_sync(0xffffffffu, ps, o);
            pd += __shfl_xor_sync(0xffffffffu, pd, o);
        }
        if ((t_col & 7) == 0 && row < N_NODES) {
            out_s[row * HEADS + head] = ps;
            out_d[row * HEADS + head] = pd;
        }
    }
}

// ----------------------------------------------------------------------------
// Fused softmax + aggregation: one warp per dst node, unroll x8.
// lane covers channels 4*lane..4*lane+3; head = lane>>3; q identical across
// the 8 lanes of a head -> den needs no reduction.
// ----------------------------------------------------------------------------
__global__ __launch_bounds__(256) void agg_fused_kernel(
    const float* __restrict__ h, const int* __restrict__ off,
    const int* __restrict__ csr, const float* __restrict__ as,
    const float* __restrict__ ad, const float* __restrict__ bias,
    float* __restrict__ out) {
    int warp = threadIdx.x >> 5;
    int lane = threadIdx.x & 31;
    int n = blockIdx.x * 8 + warp;
    if (n >= N_NODES) return;

    int head = lane >> 3;
    float ad_h = ad[n * HEADS + head];
    const float4* h4 = reinterpret_cast<const float4*>(h);

    float4 acc = make_float4(0.f, 0.f, 0.f, 0.f);
    float den = 0.f;
    int s0 = off[n], s1 = off[n + 1];

    int pos = s0;
    for (; pos + 8 <= s1; pos += 8) {
        int sa0 = csr[pos];     int sa1 = csr[pos + 1];
        int sa2 = csr[pos + 2]; int sa3 = csr[pos + 3];
        int sa4 = csr[pos + 4]; int sa5 = csr[pos + 5];
        int sa6 = csr[pos + 6]; int sa7 = csr[pos + 7];
        float e0 = as[sa0 * HEADS + head] + ad_h;
        float e1 = as[sa1 * HEADS + head] + ad_h;
        float e2 = as[sa2 * HEADS + head] + ad_h;
        float e3 = as[sa3 * HEADS + head] + ad_h;
        float e4 = as[sa4 * HEADS + head] + ad_h;
        float e5 = as[sa5 * HEADS + head] + ad_h;
        float e6 = as[sa6 * HEADS + head] + ad_h;
        float e7 = as[sa7 * HEADS + head] + ad_h;
        e0 = e0 > 0.f ? e0 : NEG_SLOPE * e0;
        e1 = e1 > 0.f ? e1 : NEG_SLOPE * e1;
        e2 = e2 > 0.f ? e2 : NEG_SLOPE * e2;
        e3 = e3 > 0.f ? e3 : NEG_SLOPE * e3;
        e4 = e4 > 0.f ? e4 : NEG_SLOPE * e4;
        e5 = e5 > 0.f ? e5 : NEG_SLOPE * e5;
        e6 = e6 > 0.f ? e6 : NEG_SLOPE * e6;
        e7 = e7 > 0.f ? e7 : NEG_SLOPE * e7;
        float q0 = __expf(e0), q1 = __expf(e1), q2 = __expf(e2), q3 = __expf(e3);
        float q4 = __expf(e4), q5 = __expf(e5), q6 = __expf(e6), q7 = __expf(e7);
        float4 h0 = h4[(size_t)sa0 * 32 + lane];
        float4 h1 = h4[(size_t)sa1 * 32 + lane];
        float4 h2 = h4[(size_t)sa2 * 32 + lane];
        float4 h3 = h4[(size_t)sa3 * 32 + lane];
        float4 h5 = h4[(size_t)sa4 * 32 + lane];
        float4 h6 = h4[(size_t)sa5 * 32 + lane];
        float4 h7 = h4[(size_t)sa6 * 32 + lane];
        float4 h8 = h4[(size_t)sa7 * 32 + lane];
        acc.x += q0 * h0.x + q1 * h1.x + q2 * h2.x + q3 * h3.x;
        acc.y += q0 * h0.y + q1 * h1.y + q2 * h2.y + q3 * h3.y;
        acc.z += q0 * h0.z + q1 * h1.z + q2 * h2.z + q3 * h3.z;
        acc.w += q0 * h0.w + q1 * h1.w + q2 * h2.w + q3 * h3.w;
        acc.x += q4 * h5.x + q5 * h6.x + q6 * h7.x + q7 * h8.x;
        acc.y += q4 * h5.y + q5 * h6.y + q6 * h7.y + q7 * h8.y;
        acc.z += q4 * h5.z + q5 * h6.z + q6 * h7.z + q7 * h8.z;
        acc.w += q4 * h5.w + q5 * h6.w + q6 * h7.w + q7 * h8.w;
        den += ((q0 + q1) + (q2 + q3)) + ((q4 + q5) + (q6 + q7));
    }
    for (; pos < s1; pos++) {
        int sa = csr[pos];
        float e = as[sa * HEADS + head] + ad_h;
        e = e > 0.f ? e : NEG_SLOPE * e;
        float q = __expf(e);
        float4 ha = h4[(size_t)sa * 32 + lane];
        acc.x += q * ha.x; acc.y += q * ha.y;
        acc.z += q * ha.z; acc.w += q * ha.w;
        den += q;
    }

    float inv = 1.f / den;   // deg >= 1 (self loop), den > 0
    float4 bv = reinterpret_cast<const float4*>(bias)[lane];
    float4 o;
    o.x = fmaxf(acc.x * inv + bv.x, 0.f);
    o.y = fmaxf(acc.y * inv + bv.y, 0.f);
    o.z = fmaxf(acc.z * inv + bv.z, 0.f);
    o.w = fmaxf(acc.w * inv + bv.w, 0.f);
    reinterpret_cast<float4*>(out)[(size_t)n * 32 + lane] = o;
}

// ----------------------------------------------------------------------------
// Launch: CSR build forked onto a side stream, overlapped with wconv+gemm0.
// ----------------------------------------------------------------------------
extern "C" void kernel_launch(void* const* d_in, const int* in_sizes, int n_in,
                              void* d_out, int out_size) {
    const float* x    = (const float*)d_in[0];
    const int*   ei   = (const int*)d_in[1];
    const float* Ws   = (const float*)d_in[2];
    const float* a_s  = (const float*)d_in[3];
    const float* a_d  = (const float*)d_in[4];
    const float* bias = (const float*)d_in[5];
    float*       out  = (float*)d_out;

    void* pv;
    cudaGetSymbolAddress(&pv, g_x0);   float* x0  = (float*)pv;
    cudaGetSymbolAddress(&pv, g_x1);   float* x1  = (float*)pv;
    cudaGetSymbolAddress(&pv, g_h);    float* h   = (float*)pv;
    cudaGetSymbolAddress(&pv, g_as);   float* as  = (float*)pv;
    cudaGetSymbolAddress(&pv, g_ad);   float* ad  = (float*)pv;
    cudaGetSymbolAddress(&pv, g_wt);   unsigned int* wt = (unsigned int*)pv;
    cudaGetSymbolAddress(&pv, g_deg);  int*   deg  = (int*)pv;
    cudaGetSymbolAddress(&pv, g_off);  int*   off  = (int*)pv;
    cudaGetSymbolAddress(&pv, g_cur);  int*   cur  = (int*)pv;
    cudaGetSymbolAddress(&pv, g_part); int*   part = (int*)pv;
    cudaGetSymbolAddress(&pv, g_poff); int*   poff = (int*)pv;
    cudaGetSymbolAddress(&pv, g_csr);  int*   csr  = (int*)pv;

    cudaFuncSetAttribute(gemm_tf32_alpha_kernel,
                         cudaFuncAttributeMaxDynamicSharedMemorySize, GEMM_SMEM);
    cudaFuncSetAttribute(gemm_tf32_alpha_kernel,
                         cudaFuncAttributePreferredSharedMemoryCarveout, 100);

    // lazily created host-side handles (device work identical every call)
    static cudaStream_t s2 = nullptr;
    static cudaEvent_t ev_fork = nullptr, ev_join = nullptr;
    if (s2 == nullptr) {
        cudaStreamCreateWithFlags(&s2, cudaStreamNonBlocking);
        cudaEventCreateWithFlags(&ev_fork, cudaEventDisableTiming);
        cudaEventCreateWithFlags(&ev_join, cudaEventDisableTiming);
    }

    // fork: CSR build on side stream
    cudaEventRecord(ev_fork, 0);
    cudaStreamWaitEvent(s2, ev_fork, 0);
    deg_one_kernel<<<(N_NODES + 255) / 256, 256, 0, s2>>>(deg);
    hist_kernel<<<(N_EDGES / 4 + 255) / 256, 256, 0, s2>>>(ei, deg);
    partial_kernel<<<NB, SB, 0, s2>>>(deg, part);
    scan_parts_kernel<<<1, 256, 0, s2>>>(part, poff, off);
    offsets_kernel<<<NB, SB, 0, s2>>>(deg, poff, off, cur);
    fill_kernel<<<(E_TOT / 4 + 255) / 256, 256, 0, s2>>>(ei, cur, csr);
    cudaEventRecord(ev_join, s2);

    // main stream: W convert + layer-0 GEMM overlap the CSR build
    wconv_kernel<<<(3 * F * F + 255) / 256, 256>>>(Ws, wt);
    gemm_tf32_alpha_kernel<<<(N_NODES + 63) / 64, 256, GEMM_SMEM>>>(
        x, wt, a_s, a_d, h, as, ad);

    // join before first aggregation
    cudaStreamWaitEvent(0, ev_join, 0);

    for (int l = 0; l < 3; l++) {
        float* xout = (l == 0) ? x0 : ((l == 1) ? x1 : out);
        agg_fused_kernel<<<(N_NODES + 7) / 8, 256>>>(
            h, off, csr, as, ad, bias + l * F, xout);
        if (l < 2) {
            gemm_tf32_alpha_kernel<<<(N_NODES + 63) / 64, 256, GEMM_SMEM>>>(
                xout, wt + (size_t)(l + 1) * F * F,
                a_s + (l + 1) * F, a_d + (l + 1) * F, h, as, ad);
        }
    }
}